// round 15
// baseline (speedup 1.0000x reference)
#include <cuda_runtime.h>
#include <cuda_fp16.h>
#include <cstdint>

// Problem constants
#define Bn 256
#define Nn 1152        // 32*6*6 input capsules
#define On 10
#define En 16
#define OE 160         // On*En
#define Dn 8
#define NC 32          // n per k_uhat block
#define K1T (Nn / NC)  // 36 n-tiles in k_uhat
#define BC 32          // b per k_uhat block
#define NTILE 64       // route tile (register-resident)
#define NTILES 18      // 1152 / 64

// Scratch (device globals)
__device__ __half g_uhat[(size_t)Bn * Nn * OE];  // ~94 MB fp16
__device__ float  g_part[K1T * Bn * OE];         // per-tile partials (36 >= 18)
__device__ float  g_v[Bn * OE];                  // v0, then v0+v1 (the logit vector)

// ---------------------------------------------------------------------------
// squash over E=16 within a warp-half. Requires fully-active warps.
__device__ __forceinline__ float squash_val(float sv) {
    float sq = sv * sv;
    sq += __shfl_xor_sync(0xffffffffu, sq, 1);
    sq += __shfl_xor_sync(0xffffffffu, sq, 2);
    sq += __shfl_xor_sync(0xffffffffu, sq, 4);
    sq += __shfl_xor_sync(0xffffffffu, sq, 8);
    return sv * sq / (1.0f + sq) / (sqrtf(sq) + 1e-6f);
}

// ---------------------------------------------------------------------------
// K1 (R4): u_hat[b,n,o,e] = sum_d x[b,n,d] * W[n,o,d,e]  (fp16 out)
//     + fused partial s0: g_part[tile][b][oe] = sum_{n in tile} u
// grid (36 n-tiles, 8 b-tiles), 320 threads = 4 b-groups x 80 (o,e-pair).
__global__ void k_uhat(const float* __restrict__ x, const float* __restrict__ W) {
    int nb = blockIdx.x * NC;
    int b0 = blockIdx.y * BC;
    int t  = threadIdx.x;              // 0..319

    __shared__ float xs[BC][NC][Dn];   // 32 KB, [b][n][d]
    for (int i = t; i < BC * NC * Dn / 4; i += 320) {  // 2048 float4
        int b = i >> 6, q = i & 63;
        float4 v = *(const float4*)(x + ((size_t)(b0 + b) * Nn + nb) * Dn + q * 4);
        int n = q >> 1, h = q & 1;
        *(float4*)(&xs[b][n][h * 4]) = v;
    }
    __syncthreads();

    int g = t / 80, p = t - g * 80;    // g: b-group (8 b each), p: (o, e-pair)
    int o = p >> 3, e2 = p & 7;        // oe = 2*p

    float2 acc[8];
#pragma unroll
    for (int b = 0; b < 8; b++) acc[b] = make_float2(0.f, 0.f);

    __half2* uh = (__half2*)g_uhat;
    for (int n = 0; n < NC; n++) {
        float2 w[8];
        const float2* wp = (const float2*)(W + (size_t)((nb + n) * On + o) * (Dn * En)) + e2;
#pragma unroll
        for (int d = 0; d < 8; d++) w[d] = wp[d * 8];  // stride En floats = 8 float2
#pragma unroll
        for (int b = 0; b < 8; b++) {
            int bb = g * 8 + b;
            float u0 = 0.f, u1 = 0.f;
#pragma unroll
            for (int d = 0; d < 8; d++) {
                float xv = xs[bb][n][d];
                u0 = fmaf(w[d].x, xv, u0);
                u1 = fmaf(w[d].y, xv, u1);
            }
            acc[b].x += u0; acc[b].y += u1;
            uh[((size_t)(b0 + bb) * Nn + nb + n) * 80 + p] = __floats2half2_rn(u0, u1);
        }
    }
#pragma unroll
    for (int b = 0; b < 8; b++) {
        int bb = g * 8 + b;
        *(float2*)(g_part + ((size_t)blockIdx.x * Bn + b0 + bb) * OE + 2 * p) = acc[b];
    }
}

// ---------------------------------------------------------------------------
// Register-resident route iteration.
// Thread layout: g = t/40 (8 n-groups of 8 n), pq = t%40, o = pq/4, q = pq%4,
// e = 4q..4q+3. Each thread holds u[n][e..e+3] for its 8 n in registers
// (8 x LDG.64, no smem staging). Logit dot over e: in-reg FMA + 2 shfl over
// the 4 q-lanes (contiguous in-warp). smem only for logits/c/partials (~11KB)
// -> 6 CTAs/SM. ITER=2 traverses (tile,b) reversed for L2-tail harvest.
template <int ITER>
__global__ __launch_bounds__(320, 6) void k_route() {
    __shared__ float b1s[NTILE * On];   // 2560 B
    __shared__ float cs [NTILE * On];   // 2560 B
    __shared__ float sp [8 * OE];       // 5120 B (8 groups x 160)

    int tile = (ITER == 2) ? (NTILES - 1 - (int)blockIdx.x) : (int)blockIdx.x;
    int b    = (ITER == 2) ? (Bn - 1 - (int)blockIdx.y)     : (int)blockIdx.y;
    int t = threadIdx.x;                // 0..319
    int g = t / 40, pq = t - g * 40;
    int o = pq >> 2, q = pq & 3;
    int n0 = tile * NTILE + g * 8;

    // v slice for my 4 e-lanes (uniform across g: L2 broadcast)
    float4 v4 = *(const float4*)(g_v + b * OE + pq * 4);

    // Phase A: u into registers, 8 x LDG.64 (MLP=8)
    uint2 u[8];
    const uint2* up = (const uint2*)(g_uhat + ((size_t)b * Nn + n0) * OE) + pq;
#pragma unroll
    for (int i = 0; i < 8; i++) u[i] = up[i * 40];

    // Phase B: logits. dot over my 4 e, then shfl-reduce over the 4 q-lanes.
#pragma unroll
    for (int i = 0; i < 8; i++) {
        float2 a0 = __half22float2(*(const __half2*)&u[i].x);
        float2 a1 = __half22float2(*(const __half2*)&u[i].y);
        float d = fmaf(a0.x, v4.x, fmaf(a0.y, v4.y, fmaf(a1.x, v4.z, a1.y * v4.w)));
        d += __shfl_xor_sync(0xffffffffu, d, 1);
        d += __shfl_xor_sync(0xffffffffu, d, 2);
        if (q == 0) b1s[(g * 8 + i) * On + o] = d;
    }
    __syncthreads();

    // Phase C: softmax over o, one thread per n
    if (t < NTILE) {
        const float* br = b1s + t * On;
        float m = br[0];
#pragma unroll
        for (int oo = 1; oo < On; oo++) m = fmaxf(m, br[oo]);
        float ex[On]; float ssum = 0.f;
#pragma unroll
        for (int oo = 0; oo < On; oo++) { ex[oo] = __expf(br[oo] - m); ssum += ex[oo]; }
        float inv = 1.0f / ssum;
        float* cr = cs + t * On;
#pragma unroll
        for (int oo = 0; oo < On; oo++) cr[oo] = ex[oo] * inv;
    }
    __syncthreads();

    // Phase D: weighted sums from registers
    float4 acc = make_float4(0.f, 0.f, 0.f, 0.f);
#pragma unroll
    for (int i = 0; i < 8; i++) {
        float c = cs[(g * 8 + i) * On + o];
        float2 a0 = __half22float2(*(const __half2*)&u[i].x);
        float2 a1 = __half22float2(*(const __half2*)&u[i].y);
        acc.x = fmaf(c, a0.x, acc.x);
        acc.y = fmaf(c, a0.y, acc.y);
        acc.z = fmaf(c, a1.x, acc.z);
        acc.w = fmaf(c, a1.y, acc.w);
    }
    // sp row is in oe order: element pq*4+j == oe o*16+4q+j
    *(float4*)(sp + g * OE + pq * 4) = acc;
    __syncthreads();

    if (t < OE) {
        float r = sp[t];
#pragma unroll
        for (int gg = 1; gg < 8; gg++) r += sp[gg * OE + t];
        g_part[((size_t)tile * Bn + b) * OE + t] = r;
    }
}

// ---------------------------------------------------------------------------
// Reduce partials -> s -> squash. Tile axis parallelized across thread groups.
// MODE 0: s0 = 0.1*sum(36 tiles) -> v0 -> g_v   (640 thr = 4 x 160)
// MODE 1: v1 = squash(sum 18); g_v += v1        (480 thr = 3 x 160)
// MODE 2: v2 -> out                             (480 thr)
template <int MODE>
__global__ void k_finish(float* __restrict__ out) {
    constexpr int NT  = (MODE == 0) ? K1T : NTILES;  // 36 / 18
    constexpr int G   = (MODE == 0) ? 4 : 3;
    constexpr int PER = NT / G;                      // 9 / 6
    __shared__ float red[G][OE];

    int b = blockIdx.x, t = threadIdx.x;             // G*160
    int g = t / OE, oe = t - g * OE;
    float acc = 0.f;
#pragma unroll
    for (int i = 0; i < PER; i++)
        acc += g_part[((size_t)(g * PER + i) * Bn + b) * OE + oe];
    red[g][oe] = acc;
    __syncthreads();

    if (t < OE) {
        float s = red[0][t];
#pragma unroll
        for (int gg = 1; gg < G; gg++) s += red[gg][t];
        if (MODE == 0)      g_v[b * OE + t]  = squash_val(s * 0.1f);
        else if (MODE == 1) g_v[b * OE + t] += squash_val(s);
        else                out[b * OE + t]  = squash_val(s);
    }
}

// ---------------------------------------------------------------------------
extern "C" void kernel_launch(void* const* d_in, const int* in_sizes, int n_in,
                              void* d_out, int out_size) {
    const float* x = (const float*)d_in[0];
    const float* W = (const float*)d_in[1];
    if (n_in >= 2 && in_sizes[0] == 1474560) {  // defensive: swapped order
        x = (const float*)d_in[1];
        W = (const float*)d_in[0];
    }
    float* out = (float*)d_out;

    k_uhat<<<dim3(K1T, Bn / BC), 320>>>(x, W);       // u_hat fp16 + s0 partials
    k_finish<0><<<Bn, 4 * OE>>>(nullptr);            // v0
    k_route<1><<<dim3(NTILES, Bn), 320>>>();         // iter 1 partials (register route)
    k_finish<1><<<Bn, 3 * OE>>>(nullptr);            // v1, g_v = v0+v1
    k_route<2><<<dim3(NTILES, Bn), 320>>>();         // iter 2 partials (reversed)
    k_finish<2><<<Bn, 3 * OE>>>(out);                // v2 -> d_out
}